// round 3
// baseline (speedup 1.0000x reference)
#include <cuda_runtime.h>
#include <cuda_bf16.h>

// GCN: 3x (h = relu(A_norm @ (h @ W) + b)) -> global mean pool -> MLP.
// CSR-by-dst built once per launch (histogram + scan + scatter), then each
// layer = dense GEMM (warp-per-row, W in SMEM) + gather-only aggregation
// (warp-per-node, register accumulate, single write). hW (12.8MB) is
// L2-resident so gathers are LTS-bound. No float atomics in the hot path.
// NOTE: harness delivers int64 inputs as int32 device buffers -> cast to int*.

#define NMAX 50000
#define EMAX 800000
#define GMAX 2048

__device__ float g_hW[NMAX * 64];      // X @ W scratch (GEMM output)
__device__ float g_h[NMAX * 64];       // layer activations (aggregate output)
__device__ float g_dinv[NMAX];         // 1/sqrt(deg+1)
__device__ int   g_deg[NMAX];          // in-degree histogram (edges only)
__device__ int   g_rowptr[NMAX + 1];   // CSR row pointers (by dst)
__device__ int   g_fill[NMAX];         // scatter cursors
__device__ int2  g_edges[EMAX];        // packed {src, __float_as_int(norm)}
__device__ float g_pool[GMAX * 64];    // pooled graph features

// ---------------------------------------------------------------------------
__global__ void init_kernel(int n) {
    int i = blockIdx.x * blockDim.x + threadIdx.x;
    if (i < n) { g_deg[i] = 0; g_fill[i] = 0; }
}

__global__ void hist_kernel(const int* __restrict__ ei, int E) {
    int e = blockIdx.x * blockDim.x + threadIdx.x;
    if (e < E) atomicAdd(&g_deg[ei[E + e]], 1);
}

__global__ void dinv_kernel(int n) {
    int i = blockIdx.x * blockDim.x + threadIdx.x;
    if (i < n) g_dinv[i] = rsqrtf((float)(g_deg[i] + 1));  // +1 self loop
}

// Single-block exclusive scan of g_deg -> g_rowptr, 4 elems/thread/chunk.
__global__ void scan_kernel(int n) {
    __shared__ int wsum[32];
    __shared__ int carry_s;
    const int tid = threadIdx.x, lane = tid & 31, wid = tid >> 5;
    if (tid == 0) carry_s = 0;
    __syncthreads();
    const int CH = 1024 * 4;
    for (int base = 0; base < n; base += CH) {
        int idx = base + tid * 4;
        int v[4];
#pragma unroll
        for (int j = 0; j < 4; j++) v[j] = (idx + j < n) ? g_deg[idx + j] : 0;
        int t = v[0] + v[1] + v[2] + v[3];
        int sc = t;
#pragma unroll
        for (int off = 1; off < 32; off <<= 1) {
            int u = __shfl_up_sync(0xffffffffu, sc, off);
            if (lane >= off) sc += u;
        }
        if (lane == 31) wsum[wid] = sc;
        __syncthreads();
        if (wid == 0) {
            int ws = wsum[lane];
#pragma unroll
            for (int off = 1; off < 32; off <<= 1) {
                int u = __shfl_up_sync(0xffffffffu, ws, off);
                if (lane >= off) ws += u;
            }
            wsum[lane] = ws;
        }
        __syncthreads();
        int carry = carry_s;
        int run = carry + (wid ? wsum[wid - 1] : 0) + sc - t;  // exclusive
#pragma unroll
        for (int j = 0; j < 4; j++) {
            if (idx + j < n) g_rowptr[idx + j] = run;
            run += v[j];
        }
        __syncthreads();
        if (tid == 1023) carry_s = carry + wsum[31];
        __syncthreads();
    }
    if (threadIdx.x == 0) g_rowptr[n] = carry_s;
}

__global__ void scatter_kernel(const int* __restrict__ ei, int E) {
    int e = blockIdx.x * blockDim.x + threadIdx.x;
    if (e < E) {
        int s = ei[e];
        int d = ei[E + e];
        float w = g_dinv[s] * g_dinv[d];
        int pos = g_rowptr[d] + atomicAdd(&g_fill[d], 1);
        g_edges[pos] = make_int2(s, __float_as_int(w));
    }
}

// ---------------------------------------------------------------------------
// Dense GEMM: g_hW[n,64] = SRC[n,K] @ W[K,64]. One warp per row; W in SMEM;
// x row held in registers, broadcast via shfl. SRC_EXT=1 -> use X param,
// SRC_EXT=0 -> read g_h. K in {32, 64}.
template <int K, int SRC_EXT>
__global__ void gemm_kernel(const float* __restrict__ X,
                            const float* __restrict__ W, int n) {
    __shared__ float Ws[K * 64];
    for (int i = threadIdx.x; i < K * 64; i += blockDim.x) Ws[i] = W[i];
    __syncthreads();
    const int lane = threadIdx.x & 31;
    const int warp = (blockIdx.x * blockDim.x + threadIdx.x) >> 5;
    const int nwarps = (gridDim.x * blockDim.x) >> 5;
    const float* src = SRC_EXT ? X : g_h;
    for (int row = warp; row < n; row += nwarps) {
        float x0 = src[(size_t)row * K + lane];
        float x1 = 0.f;
        if (K == 64) x1 = src[(size_t)row * K + 32 + lane];
        float a0 = 0.f, a1 = 0.f;
#pragma unroll
        for (int k = 0; k < 32; k++) {
            float xv = __shfl_sync(0xffffffffu, x0, k);
            a0 += xv * Ws[k * 64 + lane];
            a1 += xv * Ws[k * 64 + 32 + lane];
        }
        if (K == 64) {
#pragma unroll
            for (int k = 0; k < 32; k++) {
                float xv = __shfl_sync(0xffffffffu, x1, k);
                a0 += xv * Ws[(k + 32) * 64 + lane];
                a1 += xv * Ws[(k + 32) * 64 + 32 + lane];
            }
        }
        g_hW[(size_t)row * 64 + lane] = a0;
        g_hW[(size_t)row * 64 + 32 + lane] = a1;
    }
}

// ---------------------------------------------------------------------------
// Gather-only aggregation:
//   g_h[i] = relu(sum_e norm_e*g_hW[src_e] + dinv_i^2*g_hW[i] + b)
__global__ void aggregate_kernel(const float* __restrict__ b, int n) {
    const int lane = threadIdx.x & 31;
    const int node = (blockIdx.x * blockDim.x + threadIdx.x) >> 5;
    if (node >= n) return;
    float dn = g_dinv[node];
    float self = dn * dn;
    float a0 = self * g_hW[(size_t)node * 64 + lane];
    float a1 = self * g_hW[(size_t)node * 64 + 32 + lane];
    int p = g_rowptr[node], e = g_rowptr[node + 1];
    for (; p + 1 < e; p += 2) {   // 2-deep unroll for MLP on L2 gathers
        int2 r0 = g_edges[p];
        int2 r1 = g_edges[p + 1];
        float w0 = __int_as_float(r0.y);
        float w1 = __int_as_float(r1.y);
        const float* s0 = g_hW + (size_t)r0.x * 64;
        const float* s1 = g_hW + (size_t)r1.x * 64;
        float v00 = s0[lane], v01 = s0[32 + lane];
        float v10 = s1[lane], v11 = s1[32 + lane];
        a0 += w0 * v00; a1 += w0 * v01;
        a0 += w1 * v10; a1 += w1 * v11;
    }
    if (p < e) {
        int2 r = g_edges[p];
        float w = __int_as_float(r.y);
        const float* s = g_hW + (size_t)r.x * 64;
        a0 += w * s[lane];
        a1 += w * s[32 + lane];
    }
    a0 += b[lane];
    a1 += b[32 + lane];
    g_h[(size_t)node * 64 + lane] = fmaxf(a0, 0.f);
    g_h[(size_t)node * 64 + 32 + lane] = fmaxf(a1, 0.f);
}

// ---------------------------------------------------------------------------
__device__ __forceinline__ int lbound(const int* __restrict__ a, int n, int v) {
    int lo = 0, hi = n;
    while (lo < hi) {
        int m = (lo + hi) >> 1;
        if (a[m] < v) lo = m + 1; else hi = m;
    }
    return lo;
}

// Mean pool over sorted batch ids: one warp per graph, binary-search bounds.
__global__ void pool_kernel(const int* __restrict__ batch, int n, int G) {
    const int lane = threadIdx.x & 31;
    const int g = (blockIdx.x * blockDim.x + threadIdx.x) >> 5;
    if (g >= G) return;
    int start = lbound(batch, n, g);
    int end   = lbound(batch, n, g + 1);
    float a0 = 0.f, a1 = 0.f;
    for (int i = start; i < end; i++) {
        a0 += g_h[(size_t)i * 64 + lane];
        a1 += g_h[(size_t)i * 64 + 32 + lane];
    }
    int cnt = end - start;
    float inv = 1.f / (float)(cnt > 0 ? cnt : 1);
    g_pool[g * 64 + lane] = a0 * inv;
    g_pool[g * 64 + 32 + lane] = a1 * inv;
}

// MLP head: out = relu(pool @ lw1 + lb1) @ lw2 + lb2. One warp per graph.
__global__ void mlp_kernel(const float* __restrict__ lw1,
                           const float* __restrict__ lb1,
                           const float* __restrict__ lw2,
                           const float* __restrict__ lb2,
                           float* __restrict__ out, int G) {
    const int lane = threadIdx.x & 31;
    const int g = (blockIdx.x * blockDim.x + threadIdx.x) >> 5;
    if (g >= G) return;
    float p0 = g_pool[g * 64 + lane];
    float p1 = g_pool[g * 64 + 32 + lane];
    float a0 = lb1[lane], a1 = lb1[32 + lane];
#pragma unroll
    for (int k = 0; k < 32; k++) {
        float xv = __shfl_sync(0xffffffffu, p0, k);
        a0 += xv * lw1[k * 64 + lane];
        a1 += xv * lw1[k * 64 + 32 + lane];
    }
#pragma unroll
    for (int k = 0; k < 32; k++) {
        float xv = __shfl_sync(0xffffffffu, p1, k);
        a0 += xv * lw1[(k + 32) * 64 + lane];
        a1 += xv * lw1[(k + 32) * 64 + 32 + lane];
    }
    a0 = fmaxf(a0, 0.f);
    a1 = fmaxf(a1, 0.f);
    float o0 = a0 * lw2[lane * 2 + 0] + a1 * lw2[(lane + 32) * 2 + 0];
    float o1 = a0 * lw2[lane * 2 + 1] + a1 * lw2[(lane + 32) * 2 + 1];
#pragma unroll
    for (int off = 16; off; off >>= 1) {
        o0 += __shfl_down_sync(0xffffffffu, o0, off);
        o1 += __shfl_down_sync(0xffffffffu, o1, off);
    }
    if (lane == 0) {
        out[g * 2 + 0] = o0 + lb2[0];
        out[g * 2 + 1] = o1 + lb2[1];
    }
}

// ---------------------------------------------------------------------------
extern "C" void kernel_launch(void* const* d_in, const int* in_sizes, int n_in,
                              void* d_out, int out_size) {
    const float* x     = (const float*)d_in[0];
    const int*   ei    = (const int*)d_in[1];    // int64 in ref -> int32 on device
    const int*   batch = (const int*)d_in[2];    // int64 in ref -> int32 on device
    const float* W1 = (const float*)d_in[3];
    const float* b1 = (const float*)d_in[4];
    const float* W2 = (const float*)d_in[5];
    const float* b2 = (const float*)d_in[6];
    const float* W3 = (const float*)d_in[7];
    const float* b3 = (const float*)d_in[8];
    const float* lw1 = (const float*)d_in[9];
    const float* lb1 = (const float*)d_in[10];
    const float* lw2 = (const float*)d_in[11];
    const float* lb2 = (const float*)d_in[12];
    float* out = (float*)d_out;

    const int N = in_sizes[0] / 32;
    const int E = in_sizes[1] / 2;
    const int G = out_size / 2;

    const int T = 256;
    // --- CSR build (per launch, deterministic structure) ---
    init_kernel<<<(N + T - 1) / T, T>>>(N);
    hist_kernel<<<(E + T - 1) / T, T>>>(ei, E);
    dinv_kernel<<<(N + T - 1) / T, T>>>(N);
    scan_kernel<<<1, 1024>>>(N);
    scatter_kernel<<<(E + T - 1) / T, T>>>(ei, E);

    const int gemm_blocks = 444;  // ~3 blocks/SM, 8 warps each
    const int agg_blocks = (N * 32 + T - 1) / T;

    // --- Layer 1 ---
    gemm_kernel<32, 1><<<gemm_blocks, T>>>(x, W1, N);
    aggregate_kernel<<<agg_blocks, T>>>(b1, N);
    // --- Layer 2 ---
    gemm_kernel<64, 0><<<gemm_blocks, T>>>(x, W2, N);
    aggregate_kernel<<<agg_blocks, T>>>(b2, N);
    // --- Layer 3 ---
    gemm_kernel<64, 0><<<gemm_blocks, T>>>(x, W3, N);
    aggregate_kernel<<<agg_blocks, T>>>(b3, N);

    // --- Pool + MLP head ---
    pool_kernel<<<(G * 32 + T - 1) / T, T>>>(batch, N, G);
    mlp_kernel<<<(G * 32 + T - 1) / T, T>>>(lw1, lb1, lw2, lb2, out, G);
}

// round 4
// speedup vs baseline: 1.0863x; 1.0863x over previous
#include <cuda_runtime.h>
#include <cuda_bf16.h>

// GCN: 3x (h = relu(A_norm @ (h @ W) + b)) -> global mean pool -> MLP.
// CSR-by-dst per launch (vectorized hist + hierarchical 3-phase scan +
// vectorized scatter), then each layer = dense GEMM (warp-per-row, W in SMEM)
// + gather-only aggregation (warp-per-node, 4-deep edge unroll). hW (12.8MB)
// stays L2-resident -> gathers are LTS-bound. Pool+MLP fused. No float atomics.

#define NMAX 50000
#define EMAX 800000
#define GMAX 2048
#define SCAN_B 1024          // threads per scan block, 1 elem/thread
#define NB_MAX 64            // max scan blocks (ceil(50000/1024)=49)

__device__ float g_hW[NMAX * 64];      // X @ W scratch (GEMM output)
__device__ float g_h[NMAX * 64];       // layer activations (aggregate output)
__device__ float g_dinv[NMAX];         // 1/sqrt(deg+1)
__device__ int   g_deg[NMAX];          // in-degree histogram (edges only)
__device__ int   g_rowptr[NMAX + 1];   // CSR row pointers (by dst)
__device__ int   g_fill[NMAX];         // scatter cursors
__device__ int2  g_edges[EMAX];        // packed {src, __float_as_int(norm)}
__device__ int   g_bsum[NB_MAX];       // scan block sums

// ---------------------------------------------------------------------------
__global__ void init_kernel(int n) {
    int i = blockIdx.x * blockDim.x + threadIdx.x;
    if (i < n) { g_deg[i] = 0; g_fill[i] = 0; }
}

// Histogram of dst, 4 edges per thread (int4 loads when aligned).
__global__ void hist_kernel(const int* __restrict__ ei, int E) {
    int base = (blockIdx.x * blockDim.x + threadIdx.x) * 4;
    if ((E & 3) == 0) {
        if (base < E) {
            int4 d = *reinterpret_cast<const int4*>(ei + E + base);
            atomicAdd(&g_deg[d.x], 1);
            atomicAdd(&g_deg[d.y], 1);
            atomicAdd(&g_deg[d.z], 1);
            atomicAdd(&g_deg[d.w], 1);
        }
    } else {
#pragma unroll
        for (int j = 0; j < 4; j++)
            if (base + j < E) atomicAdd(&g_deg[ei[E + base + j]], 1);
    }
}

// --- hierarchical exclusive scan of g_deg -> g_rowptr -----------------------
__global__ void scanA_kernel(int n) {        // per-block reduce -> g_bsum
    __shared__ int ws[32];
    const int lane = threadIdx.x & 31, wid = threadIdx.x >> 5;
    int idx = blockIdx.x * SCAN_B + threadIdx.x;
    int v = (idx < n) ? g_deg[idx] : 0;
#pragma unroll
    for (int off = 16; off; off >>= 1) v += __shfl_down_sync(0xffffffffu, v, off);
    if (lane == 0) ws[wid] = v;
    __syncthreads();
    if (wid == 0) {
        int s = ws[lane];
#pragma unroll
        for (int off = 16; off; off >>= 1) s += __shfl_down_sync(0xffffffffu, s, off);
        if (lane == 0) g_bsum[blockIdx.x] = s;
    }
}

__global__ void scanB_kernel(int nb) {       // 1 warp scans block sums (nb<=64)
    const int lane = threadIdx.x;
    int v0 = (2 * lane     < nb) ? g_bsum[2 * lane]     : 0;
    int v1 = (2 * lane + 1 < nb) ? g_bsum[2 * lane + 1] : 0;
    int t = v0 + v1, sc = t;
#pragma unroll
    for (int off = 1; off < 32; off <<= 1) {
        int u = __shfl_up_sync(0xffffffffu, sc, off);
        if (lane >= off) sc += u;
    }
    int ex = sc - t;
    if (2 * lane     < nb) g_bsum[2 * lane]     = ex;
    if (2 * lane + 1 < nb) g_bsum[2 * lane + 1] = ex + v0;
}

__global__ void scanC_kernel(int n) {        // rescan + offset; also dinv
    __shared__ int ws[32];
    const int lane = threadIdx.x & 31, wid = threadIdx.x >> 5;
    int idx = blockIdx.x * SCAN_B + threadIdx.x;
    int v = (idx < n) ? g_deg[idx] : 0;
    int sc = v;
#pragma unroll
    for (int off = 1; off < 32; off <<= 1) {
        int u = __shfl_up_sync(0xffffffffu, sc, off);
        if (lane >= off) sc += u;
    }
    if (lane == 31) ws[wid] = sc;
    __syncthreads();
    if (wid == 0) {
        int s = ws[lane];
#pragma unroll
        for (int off = 1; off < 32; off <<= 1) {
            int u = __shfl_up_sync(0xffffffffu, s, off);
            if (lane >= off) s += u;
        }
        ws[lane] = s;
    }
    __syncthreads();
    int off = g_bsum[blockIdx.x] + (wid ? ws[wid - 1] : 0);
    int ex = off + sc - v;
    if (idx < n) {
        g_rowptr[idx] = ex;
        g_dinv[idx] = rsqrtf((float)(v + 1));   // +1 self loop
        if (idx == n - 1) g_rowptr[n] = ex + v;
    }
}

// Scatter edges into CSR slots, 4 edges per thread.
__global__ void scatter_kernel(const int* __restrict__ ei, int E) {
    int base = (blockIdx.x * blockDim.x + threadIdx.x) * 4;
    if ((E & 3) == 0) {
        if (base < E) {
            int4 s4 = *reinterpret_cast<const int4*>(ei + base);
            int4 d4 = *reinterpret_cast<const int4*>(ei + E + base);
            int ss[4] = {s4.x, s4.y, s4.z, s4.w};
            int dd[4] = {d4.x, d4.y, d4.z, d4.w};
#pragma unroll
            for (int j = 0; j < 4; j++) {
                float w = g_dinv[ss[j]] * g_dinv[dd[j]];
                int pos = g_rowptr[dd[j]] + atomicAdd(&g_fill[dd[j]], 1);
                g_edges[pos] = make_int2(ss[j], __float_as_int(w));
            }
        }
    } else {
#pragma unroll
        for (int j = 0; j < 4; j++) {
            if (base + j < E) {
                int s = ei[base + j], d = ei[E + base + j];
                float w = g_dinv[s] * g_dinv[d];
                int pos = g_rowptr[d] + atomicAdd(&g_fill[d], 1);
                g_edges[pos] = make_int2(s, __float_as_int(w));
            }
        }
    }
}

// ---------------------------------------------------------------------------
// Dense GEMM: g_hW[n,64] = SRC[n,K] @ W[K,64]. One warp per row; W in SMEM.
template <int K, int SRC_EXT>
__global__ void gemm_kernel(const float* __restrict__ X,
                            const float* __restrict__ W, int n) {
    __shared__ float Ws[K * 64];
    for (int i = threadIdx.x; i < K * 64; i += blockDim.x) Ws[i] = W[i];
    __syncthreads();
    const int lane = threadIdx.x & 31;
    const int warp = (blockIdx.x * blockDim.x + threadIdx.x) >> 5;
    const int nwarps = (gridDim.x * blockDim.x) >> 5;
    const float* src = SRC_EXT ? X : g_h;
    for (int row = warp; row < n; row += nwarps) {
        float x0 = src[(size_t)row * K + lane];
        float x1 = 0.f;
        if (K == 64) x1 = src[(size_t)row * K + 32 + lane];
        float a0 = 0.f, a1 = 0.f;
#pragma unroll
        for (int k = 0; k < 32; k++) {
            float xv = __shfl_sync(0xffffffffu, x0, k);
            a0 += xv * Ws[k * 64 + lane];
            a1 += xv * Ws[k * 64 + 32 + lane];
        }
        if (K == 64) {
#pragma unroll
            for (int k = 0; k < 32; k++) {
                float xv = __shfl_sync(0xffffffffu, x1, k);
                a0 += xv * Ws[(k + 32) * 64 + lane];
                a1 += xv * Ws[(k + 32) * 64 + 32 + lane];
            }
        }
        g_hW[(size_t)row * 64 + lane] = a0;
        g_hW[(size_t)row * 64 + 32 + lane] = a1;
    }
}

// ---------------------------------------------------------------------------
// Gather-only aggregation, 4-deep edge unroll (8 outstanding 128B gathers):
//   g_h[i] = relu(sum_e norm_e*g_hW[src_e] + dinv_i^2*g_hW[i] + b)
__global__ void aggregate_kernel(const float* __restrict__ b, int n) {
    const int lane = threadIdx.x & 31;
    const int node = (blockIdx.x * blockDim.x + threadIdx.x) >> 5;
    if (node >= n) return;
    float dn = g_dinv[node];
    float self = dn * dn;
    float a0 = self * g_hW[(size_t)node * 64 + lane];
    float a1 = self * g_hW[(size_t)node * 64 + 32 + lane];
    int p = g_rowptr[node];
    const int e = g_rowptr[node + 1];
    const int m = p + ((e - p) & ~3);
    for (; p < m; p += 4) {
        int2 r0 = g_edges[p];
        int2 r1 = g_edges[p + 1];
        int2 r2 = g_edges[p + 2];
        int2 r3 = g_edges[p + 3];
        const float* s0 = g_hW + (size_t)r0.x * 64;
        const float* s1 = g_hW + (size_t)r1.x * 64;
        const float* s2 = g_hW + (size_t)r2.x * 64;
        const float* s3 = g_hW + (size_t)r3.x * 64;
        float v00 = s0[lane], v01 = s0[32 + lane];
        float v10 = s1[lane], v11 = s1[32 + lane];
        float v20 = s2[lane], v21 = s2[32 + lane];
        float v30 = s3[lane], v31 = s3[32 + lane];
        float w0 = __int_as_float(r0.y), w1 = __int_as_float(r1.y);
        float w2 = __int_as_float(r2.y), w3 = __int_as_float(r3.y);
        a0 += w0 * v00; a1 += w0 * v01;
        a0 += w1 * v10; a1 += w1 * v11;
        a0 += w2 * v20; a1 += w2 * v21;
        a0 += w3 * v30; a1 += w3 * v31;
    }
    for (; p < e; p++) {
        int2 r = g_edges[p];
        float w = __int_as_float(r.y);
        const float* s = g_hW + (size_t)r.x * 64;
        a0 += w * s[lane];
        a1 += w * s[32 + lane];
    }
    a0 += b[lane];
    a1 += b[32 + lane];
    g_h[(size_t)node * 64 + lane] = fmaxf(a0, 0.f);
    g_h[(size_t)node * 64 + 32 + lane] = fmaxf(a1, 0.f);
}

// ---------------------------------------------------------------------------
__device__ __forceinline__ int lbound(const int* __restrict__ a, int n, int v) {
    int lo = 0, hi = n;
    while (lo < hi) {
        int m = (lo + hi) >> 1;
        if (a[m] < v) lo = m + 1; else hi = m;
    }
    return lo;
}

// Fused mean-pool + MLP head. One warp per graph (batch ids sorted).
__global__ void pool_mlp_kernel(const int* __restrict__ batch,
                                const float* __restrict__ lw1,
                                const float* __restrict__ lb1,
                                const float* __restrict__ lw2,
                                const float* __restrict__ lb2,
                                float* __restrict__ out, int n, int G) {
    const int lane = threadIdx.x & 31;
    const int g = (blockIdx.x * blockDim.x + threadIdx.x) >> 5;
    if (g >= G) return;
    int start = lbound(batch, n, g);
    int end   = lbound(batch, n, g + 1);
    float p0 = 0.f, p1 = 0.f;
    for (int i = start; i < end; i++) {
        p0 += g_h[(size_t)i * 64 + lane];
        p1 += g_h[(size_t)i * 64 + 32 + lane];
    }
    int cnt = end - start;
    float inv = 1.f / (float)(cnt > 0 ? cnt : 1);
    p0 *= inv; p1 *= inv;

    float a0 = lb1[lane], a1 = lb1[32 + lane];
#pragma unroll
    for (int k = 0; k < 32; k++) {
        float xv = __shfl_sync(0xffffffffu, p0, k);
        a0 += xv * lw1[k * 64 + lane];
        a1 += xv * lw1[k * 64 + 32 + lane];
    }
#pragma unroll
    for (int k = 0; k < 32; k++) {
        float xv = __shfl_sync(0xffffffffu, p1, k);
        a0 += xv * lw1[(k + 32) * 64 + lane];
        a1 += xv * lw1[(k + 32) * 64 + 32 + lane];
    }
    a0 = fmaxf(a0, 0.f);
    a1 = fmaxf(a1, 0.f);
    float o0 = a0 * lw2[lane * 2 + 0] + a1 * lw2[(lane + 32) * 2 + 0];
    float o1 = a0 * lw2[lane * 2 + 1] + a1 * lw2[(lane + 32) * 2 + 1];
#pragma unroll
    for (int off = 16; off; off >>= 1) {
        o0 += __shfl_down_sync(0xffffffffu, o0, off);
        o1 += __shfl_down_sync(0xffffffffu, o1, off);
    }
    if (lane == 0) {
        out[g * 2 + 0] = o0 + lb2[0];
        out[g * 2 + 1] = o1 + lb2[1];
    }
}

// ---------------------------------------------------------------------------
extern "C" void kernel_launch(void* const* d_in, const int* in_sizes, int n_in,
                              void* d_out, int out_size) {
    const float* x     = (const float*)d_in[0];
    const int*   ei    = (const int*)d_in[1];    // int64 ref -> int32 device
    const int*   batch = (const int*)d_in[2];
    const float* W1 = (const float*)d_in[3];
    const float* b1 = (const float*)d_in[4];
    const float* W2 = (const float*)d_in[5];
    const float* b2 = (const float*)d_in[6];
    const float* W3 = (const float*)d_in[7];
    const float* b3 = (const float*)d_in[8];
    const float* lw1 = (const float*)d_in[9];
    const float* lb1 = (const float*)d_in[10];
    const float* lw2 = (const float*)d_in[11];
    const float* lb2 = (const float*)d_in[12];
    float* out = (float*)d_out;

    const int N = in_sizes[0] / 32;
    const int E = in_sizes[1] / 2;
    const int G = out_size / 2;

    const int T = 256;
    const int nb = (N + SCAN_B - 1) / SCAN_B;        // scan blocks (<=64)
    const int e4 = (E + 3) / 4;                       // 4-edge threads

    // --- CSR build ---
    init_kernel<<<(N + T - 1) / T, T>>>(N);
    hist_kernel<<<(e4 + T - 1) / T, T>>>(ei, E);
    scanA_kernel<<<nb, SCAN_B>>>(N);
    scanB_kernel<<<1, 32>>>(nb);
    scanC_kernel<<<nb, SCAN_B>>>(N);
    scatter_kernel<<<(e4 + T - 1) / T, T>>>(ei, E);

    const int gemm_blocks = 444;
    const int agg_blocks = (N * 32 + T - 1) / T;

    // --- Layer 1 ---
    gemm_kernel<32, 1><<<gemm_blocks, T>>>(x, W1, N);
    aggregate_kernel<<<agg_blocks, T>>>(b1, N);
    // --- Layer 2 ---
    gemm_kernel<64, 0><<<gemm_blocks, T>>>(x, W2, N);
    aggregate_kernel<<<agg_blocks, T>>>(b2, N);
    // --- Layer 3 ---
    gemm_kernel<64, 0><<<gemm_blocks, T>>>(x, W3, N);
    aggregate_kernel<<<agg_blocks, T>>>(b3, N);

    // --- Fused pool + MLP head ---
    pool_mlp_kernel<<<(G * 32 + T - 1) / T, T>>>(batch, lw1, lb1, lw2, lb2,
                                                 out, N, G);
}